// round 5
// baseline (speedup 1.0000x reference)
#include <cuda_runtime.h>
#include <cuda_pipeline.h>

typedef unsigned long long ull;

// Problem dims
#define NC_  31
#define NXL  256
#define NYL  256
#define NO_  3
#define KXL  17
#define KYL  17
#define NG_  (NO_ * NC_)   // 93
#define WIN_ 9

// Compact weights: per (o,c) group a 9x9 tile of broadcast (v,v) float2 pairs
__device__ float2 g_w2[NG_ * 81];
__device__ int    g_ori[NG_];   // (kx0 << 8) | ky0

// ---------------------------------------------------------------------------
// Prep A: window origin per group = min (kx, ky) over its 81 locations.
// Locations are group-contiguous (81 per group) in the dataset.
// ---------------------------------------------------------------------------
__global__ void prep_origins(const int* __restrict__ loc) {
    int g = blockIdx.x * blockDim.x + threadIdx.x;
    if (g < NG_) {
        int kxm = 1 << 30, kym = 1 << 30;
#pragma unroll 1
        for (int t = 0; t < 81; ++t) {
            int idx = loc[g * 81 + t];
            int ky = idx % KYL;
            int kx = (idx / KYL) % KXL;
            kxm = min(kxm, kx);
            kym = min(kym, ky);
        }
        g_ori[g] = (kxm << 8) | kym;
    }
}

// Prep B: scatter relu(values) as broadcast (v,v) pairs into compact tiles.
__global__ void prep_scatter(const float* __restrict__ vk,
                             const int* __restrict__ loc, int nloc) {
    int i = blockIdx.x * blockDim.x + threadIdx.x;
    if (i < nloc) {
        int idx = loc[i];
        float v = fmaxf(vk[i], 0.0f);
        int ky = idx % KYL; int t = idx / KYL;
        int kx = t % KXL;   int g = t / KXL;
        int ori = g_ori[g];
        g_w2[g * 81 + (kx - (ori >> 8)) * WIN_ + (ky - (ori & 255))] =
            make_float2(v, v);
    }
}

// ---------------------------------------------------------------------------
// Main conv. Block = 256 threads, output tile 32 rows x 128 cols per (b,o).
// cp.async staging with hoisted edge predicates (only k=0 / k=16 column
// tested) and compile-time-decomposed swizzle (two dst base pointers).
// Inner math: packed fma.rn.f32x2, dual-phase accumulators, all operand
// addresses immediate-folded off 6 per-thread bases. Weights via LDS.128.
// ---------------------------------------------------------------------------
#define TH 32
#define TW 128
#define SRO 40                 // staged rows (TH + 8)
#define SWF 160                // smem row stride in floats
#define TILE_F (SRO * SWF)     // 6400 floats
#define TILE_B (TILE_F * 4)    // 25600 bytes
#define WPAD 10                // weight row stride in ull
#define WBUF (WIN_ * WPAD)     // 90 ull
#define SMEM_BYTES (2 * TILE_B + 2 * WBUF * 8 + NC_ * 4)  // 52764

__device__ __forceinline__ int swz_unit(int cu) {
    return cu ^ ((cu >> 3) & 7);
}

__global__ void __launch_bounds__(256, 3) conv_kernel(
        const float* __restrict__ x, float* __restrict__ out) {
    extern __shared__ float smem[];
    char* buf0 = (char*)smem;
    char* buf1 = buf0 + TILE_B;
    char* wb0  = buf1 + TILE_B;
    char* wb1  = wb0 + WBUF * 8;
    int*  s_ori = (int*)(wb1 + WBUF * 8);

    const int tid = threadIdx.x;
    const int tx  = tid & 7;          // 16-col group
    const int ty  = tid >> 3;         // output row 0..31
    const int txq = tx >> 2, tx3 = tx & 3;

    const int o  = blockIdx.y;
    const int b  = blockIdx.z;
    const int i0 = (blockIdx.x >> 1) * TH;
    const int j0 = (blockIdx.x & 1) * TW;

    if (tid < NC_) s_ori[tid] = g_ori[o * NC_ + tid];
    __syncthreads();

    const float* __restrict__ xb = x + (size_t)b * NC_ * NXL * NYL;
    const int wdoff = ((tid / WIN_) * WPAD + tid % WIN_) * 8;  // weight dst

    // ---- async staging of one channel ----
    auto stage = [&](int c, char* tbuf, char* wbuf) {
        const int ori = s_ori[c];
        const int kx0 = ori >> 8, ky0 = ori & 255;
        const float* __restrict__ xc = xb + (size_t)c * NXL * NYL;
        const int ri0  = i0 + kx0 - 8;
        const int colb = j0 + ky0 - 8 + tx;   // gmem col for k=0
#pragma unroll
        for (int pass = 0; pass < 2; ++pass) {
            if (pass == 1 && ty >= 8) break;
            const int r  = ty + pass * 32;
            const int gi = ri0 + r;
            const bool rowok = (unsigned)gi < NXL;
            const int gic = min(max(gi, 0), NXL - 1);
            const float* gp = xc + gic * NYL + colb;   // valid for k>=1 derefs
            char* pd0 = tbuf + r * (SWF * 4) + tx3 * 4 + txq * 16;
            char* pd1 = tbuf + r * (SWF * 4) + tx3 * 4 + (txq ^ 1) * 16;
            const unsigned zm = rowok ? 0u : 4u;       // mid-k zfill
            // k = 0 : left-edge test
            {
                unsigned z0 = (rowok && colb >= 0) ? 0u : 4u;
                const float* s0 = z0 ? xc : gp;
                __pipeline_memcpy_async(pd0, s0, 4, z0);
            }
#pragma unroll
            for (int k = 1; k < 16; ++k) {
                const int C = k >> 2;                     // compile-time
                const int imm = ((2 * k) ^ (C & ~1)) * 16;
                char* pd = (C & 1) ? pd1 : pd0;
                __pipeline_memcpy_async(pd + imm, gp + 8 * k, 4, zm);
            }
            // k = 16 : right-edge test (dst offset (32^4)*16 = 576, pd0)
            {
                unsigned z16 = (rowok && colb + 128 < NYL) ? 0u : 4u;
                const float* s16 = z16 ? xc : (gp + 128);
                __pipeline_memcpy_async(pd0 + 576, s16, 4, z16);
            }
        }
        if (tid < 81) {
            const ull* wsrc = ((const ull*)g_w2)
                            + (size_t)(o * NC_ + c) * 81 + tid;
            __pipeline_memcpy_async(wbuf + wdoff, wsrc, 8);
        }
        __pipeline_commit();
    };

    // per-thread E base byte offsets (row/u-independent)
    int offs[6];
#pragma unroll
    for (int k = 0; k < 6; ++k)
        offs[k] = ty * (SWF * 4) + swz_unit(4 * tx + k) * 16;

    // accA[j] = (out[2j], out[2j+1]); accB[i] = (out[2i-1], out[2i])
    ull accA[8], accB[9];
#pragma unroll
    for (int j = 0; j < 8; ++j) accA[j] = 0ull;
#pragma unroll
    for (int i = 0; i < 9; ++i) accB[i] = 0ull;

    stage(0, buf0, wb0);

    for (int c = 0; c < NC_; ++c) {
        __pipeline_wait_prior(0);
        __syncthreads();
        if (c + 1 < NC_)
            stage(c + 1, (c & 1) ? buf0 : buf1, (c & 1) ? wb0 : wb1);

        const char* tb = (c & 1) ? buf1 : buf0;
        const longlong2* wv = (const longlong2*)((c & 1) ? wb1 : wb0);

#pragma unroll
        for (int u = 0; u < WIN_; ++u) {
            ull E[12];
#pragma unroll
            for (int k = 0; k < 6; ++k) {
                longlong2 L = *(const longlong2*)(tb + offs[k] + u * (SWF * 4));
                E[2 * k]     = (ull)L.x;
                E[2 * k + 1] = (ull)L.y;
            }
            longlong2 W[5];
#pragma unroll
            for (int t = 0; t < 5; ++t) W[t] = wv[u * 5 + t];

#pragma unroll
            for (int t = 0; t < 5; ++t) {
                const ull we = (ull)W[t].x;               // even tap v = 2t
#pragma unroll
                for (int j = 0; j < 8; ++j)
                    asm("fma.rn.f32x2 %0, %1, %2, %0;"
                        : "+l"(accA[j]) : "l"(E[j + t]), "l"(we));
                if (t < 4) {                              // odd tap v = 2t+1
                    const ull wo = (ull)W[t].y;
#pragma unroll
                    for (int i = 0; i < 9; ++i)
                        asm("fma.rn.f32x2 %0, %1, %2, %0;"
                            : "+l"(accB[i]) : "l"(E[i + t]), "l"(wo));
                }
            }
        }
        __syncthreads();   // readers done before next channel overwrites
    }

    // ---- epilogue: merge dual-phase accumulators, write 16 cols ----
    float res[16];
#pragma unroll
    for (int j = 0; j < 8; ++j) {
        float aLo = __uint_as_float((unsigned)(accA[j] & 0xffffffffull));
        float aHi = __uint_as_float((unsigned)(accA[j] >> 32));
        float bHi = __uint_as_float((unsigned)(accB[j] >> 32));
        float bLo = __uint_as_float((unsigned)(accB[j + 1] & 0xffffffffull));
        res[2 * j]     = aLo + bHi;
        res[2 * j + 1] = aHi + bLo;
    }
    float* op = out + ((size_t)(b * NO_ + o) * NXL + (i0 + ty)) * NYL
                    + j0 + tx * 16;
#pragma unroll
    for (int q = 0; q < 4; ++q)
        reinterpret_cast<float4*>(op)[q] =
            make_float4(res[4 * q], res[4 * q + 1],
                        res[4 * q + 2], res[4 * q + 3]);
}

// ---------------------------------------------------------------------------
extern "C" void kernel_launch(void* const* d_in, const int* in_sizes, int n_in,
                              void* d_out, int out_size) {
    const float* x   = (const float*)d_in[0];
    const float* vk  = (const float*)d_in[1];
    const int*   loc = (const int*)d_in[2];
    float* out = (float*)d_out;

    int nloc = in_sizes[2];
    int batch = in_sizes[0] / (NC_ * NXL * NYL);

    cudaFuncSetAttribute(conv_kernel,
                         cudaFuncAttributeMaxDynamicSharedMemorySize,
                         SMEM_BYTES);

    prep_origins<<<1, 128>>>(loc);
    prep_scatter<<<(nloc + 255) / 256, 256>>>(vk, loc, nloc);

    dim3 grid((NXL / TH) * (NYL / TW), NO_, batch);  // (16, 3, 16)
    conv_kernel<<<grid, 256, SMEM_BYTES>>>(x, out);
}

// round 6
// speedup vs baseline: 1.1012x; 1.1012x over previous
#include <cuda_runtime.h>
#include <cuda_pipeline.h>

typedef unsigned long long ull;

// Problem dims
#define NC_  31
#define NXL  256
#define NYL  256
#define NO_  3
#define KXL  17
#define KYL  17
#define NG_  (NO_ * NC_)   // 93
#define WIN_ 9

// Compact weights: per (o,c) group a 9x9 tile of broadcast (v,v) float2 pairs
__device__ float2 g_w2[NG_ * 81];
__device__ int    g_ori[NG_];   // (kx0 << 8) | ky0

// ---------------------------------------------------------------------------
// Prep A: window origin per group, one warp per group + shfl-min reduce.
// Locations are group-contiguous (81 per group) in the dataset.
// ---------------------------------------------------------------------------
__global__ void prep_origins(const int* __restrict__ loc) {
    int w    = (blockIdx.x * blockDim.x + threadIdx.x) >> 5;
    int lane = threadIdx.x & 31;
    if (w < NG_) {
        int kxm = 1 << 30, kym = 1 << 30;
        for (int t = lane; t < 81; t += 32) {
            int idx = loc[w * 81 + t];
            int ky = idx % KYL;
            int kx = (idx / KYL) % KXL;
            kxm = min(kxm, kx);
            kym = min(kym, ky);
        }
#pragma unroll
        for (int off = 16; off; off >>= 1) {
            kxm = min(kxm, __shfl_xor_sync(0xffffffffu, kxm, off));
            kym = min(kym, __shfl_xor_sync(0xffffffffu, kym, off));
        }
        if (lane == 0) g_ori[w] = (kxm << 8) | kym;
    }
}

// Prep B: scatter relu(values) as broadcast (v,v) pairs into compact tiles.
__global__ void prep_scatter(const float* __restrict__ vk,
                             const int* __restrict__ loc, int nloc) {
    int i = blockIdx.x * blockDim.x + threadIdx.x;
    if (i < nloc) {
        int idx = loc[i];
        float v = fmaxf(vk[i], 0.0f);
        int ky = idx % KYL; int t = idx / KYL;
        int kx = t % KXL;   int g = t / KXL;
        int ori = g_ori[g];
        g_w2[g * 81 + (kx - (ori >> 8)) * WIN_ + (ky - (ori & 255))] =
            make_float2(v, v);
    }
}

// ---------------------------------------------------------------------------
// Main conv. Block = 256 threads, tile 32 rows x 128 cols per (b,o).
// Staging origin is 8B-aligned (A = j0 + (ky0 & ~1) - 8); residual parity
// S = ky0 & 1 is absorbed by the dual-phase accumulator assignment, selected
// per channel between two templated bodies. Staging: 8B cp.async, zero-fill
// at edges. E loads: 6-7 LDS.128 of the XOR-swizzled tile per tap-row, with
// next-row units loaded into dead pair slots (software pipeline, no extra
// register pressure). Inner math: packed fma.rn.f32x2.
// ---------------------------------------------------------------------------
#define TH 32
#define TW 128
#define SRO 40                 // staged rows (TH + 8)
#define SWF 160                // smem row stride in floats
#define ROWB (SWF * 4)         // 640 bytes
#define TILE_B (SRO * ROWB)    // 25600 bytes
#define WPAD 10                // weight row stride in ull
#define WBUF (WIN_ * WPAD)     // 90 ull
#define SMEM_BYTES (2 * TILE_B + 2 * WBUF * 8 + NC_ * 4)  // 52764

#define FMA2(acc, a, b) \
    asm("fma.rn.f32x2 %0, %1, %2, %0;" : "+l"(acc) : "l"(a), "l"(b))

__device__ __forceinline__ int swz_unit(int cu) {
    return cu ^ ((cu >> 3) & 7);
}

// Load one swizzled 16B unit as a pair of ulls.
__device__ __forceinline__ void ldE(const char* p, ull& a, ull& b) {
    longlong2 L = *(const longlong2*)p;
    a = (ull)L.x; b = (ull)L.y;
}

// Channel math, parity variant SV = ky0 & 1.
// P[q] = input float pair (16tx+2q, 16tx+2q+1) of the current tap row.
// accA[j] = (out[2j], out[2j+1]); accB[i] = (out[2i-1], out[2i]).
template<int SV>
__device__ __forceinline__ void channel_math(
        const char* __restrict__ tb, const ull* __restrict__ wv,
        const int* offs, ull* accA, ull* accB) {
    ull P[14];
#pragma unroll
    for (int e = 0; e < 5; ++e)
        ldE(tb + offs[e], P[2 * e], P[2 * e + 1]);

#pragma unroll
    for (int u = 0; u < 9; ++u) {
        const int ro = u * ROWB;
        const int rn = ro + ROWB;
        const ull* wr = wv + u * WPAD;
        ull N[10];
        ldE(tb + offs[5] + ro, P[10], P[11]);          // unit 5 JIT
        if (SV == 1)
            ldE(tb + offs[6] + ro, P[12], P[13]);      // unit 6 JIT

        if (SV == 0) {
            ull wa, wb;
            wa = wr[0];
#pragma unroll
            for (int j = 0; j < 8; ++j) FMA2(accA[j], P[j], wa);
            wb = wr[1];
#pragma unroll
            for (int i = 0; i < 9; ++i) FMA2(accB[i], P[i], wb);
            wa = wr[2];
#pragma unroll
            for (int j = 0; j < 8; ++j) FMA2(accA[j], P[1 + j], wa);
            wb = wr[3];
#pragma unroll
            for (int i = 0; i < 9; ++i) FMA2(accB[i], P[1 + i], wb);
            if (u < 8) ldE(tb + offs[0] + rn, N[0], N[1]);   // unit0 next
            wa = wr[4];
#pragma unroll
            for (int j = 0; j < 8; ++j) FMA2(accA[j], P[2 + j], wa);
            wb = wr[5];
#pragma unroll
            for (int i = 0; i < 9; ++i) FMA2(accB[i], P[2 + i], wb);
            wa = wr[6];
#pragma unroll
            for (int j = 0; j < 8; ++j) FMA2(accA[j], P[3 + j], wa);
            wb = wr[7];
#pragma unroll
            for (int i = 0; i < 9; ++i) FMA2(accB[i], P[3 + i], wb);
            if (u < 8) ldE(tb + offs[1] + rn, N[2], N[3]);   // unit1 next
            wa = wr[8];
#pragma unroll
            for (int j = 0; j < 8; ++j) FMA2(accA[j], P[4 + j], wa);
        } else {
            ull wa, wb;
            wb = wr[0];
#pragma unroll
            for (int i = 0; i < 9; ++i) FMA2(accB[i], P[i], wb);
            wa = wr[1];
#pragma unroll
            for (int j = 0; j < 8; ++j) FMA2(accA[j], P[1 + j], wa);
            wb = wr[2];
#pragma unroll
            for (int i = 0; i < 9; ++i) FMA2(accB[i], P[1 + i], wb);
            wa = wr[3];
#pragma unroll
            for (int j = 0; j < 8; ++j) FMA2(accA[j], P[2 + j], wa);
            if (u < 8) ldE(tb + offs[0] + rn, N[0], N[1]);   // unit0 next
            wb = wr[4];
#pragma unroll
            for (int i = 0; i < 9; ++i) FMA2(accB[i], P[2 + i], wb);
            wa = wr[5];
#pragma unroll
            for (int j = 0; j < 8; ++j) FMA2(accA[j], P[3 + j], wa);
            wb = wr[6];
#pragma unroll
            for (int i = 0; i < 9; ++i) FMA2(accB[i], P[3 + i], wb);
            wa = wr[7];
#pragma unroll
            for (int j = 0; j < 8; ++j) FMA2(accA[j], P[4 + j], wa);
            if (u < 8) ldE(tb + offs[1] + rn, N[2], N[3]);   // unit1 next
            wb = wr[8];
#pragma unroll
            for (int i = 0; i < 9; ++i) FMA2(accB[i], P[4 + i], wb);
        }

        if (u < 8) {
            ldE(tb + offs[2] + rn, N[4], N[5]);
            ldE(tb + offs[3] + rn, N[6], N[7]);
            ldE(tb + offs[4] + rn, N[8], N[9]);
#pragma unroll
            for (int k = 0; k < 10; ++k) P[k] = N[k];
        }
    }
}

__global__ void __launch_bounds__(256, 3) conv_kernel(
        const float* __restrict__ x, float* __restrict__ out) {
    extern __shared__ float smem[];
    char* buf0 = (char*)smem;
    char* buf1 = buf0 + TILE_B;
    char* wb0  = buf1 + TILE_B;
    char* wb1  = wb0 + WBUF * 8;
    int*  s_ori = (int*)(wb1 + WBUF * 8);

    const int tid = threadIdx.x;
    const int tx  = tid & 7;          // 16-col group
    const int ty  = tid >> 3;         // output row 0..31

    const int o  = blockIdx.y;
    const int b  = blockIdx.z;
    const int i0 = (blockIdx.x >> 1) * TH;
    const int j0 = (blockIdx.x & 1) * TW;

    if (tid < NC_) s_ori[tid] = g_ori[o * NC_ + tid];
    __syncthreads();

    const float* __restrict__ xb = x + (size_t)b * NC_ * NXL * NYL;
    const int wdoff = ((tid / WIN_) * WPAD + tid % WIN_) * 8;
    const int half8 = (tx & 1) * 8;
    const int thcu  = tx >> 1;

    // ---- async staging of one channel (8B granular, aligned origin) ----
    auto stage = [&](int c, char* tbuf, char* wbuf) {
        const int ori = s_ori[c];
        const int kx0 = ori >> 8, ky0 = ori & 255;
        const int A   = j0 + (ky0 & ~1) - 8;   // even, 8B-aligned gmem origin
        const int ri0 = i0 + kx0 - 8;
        const float* __restrict__ xc = xb + (size_t)c * (NXL * NYL);
#pragma unroll
        for (int pass = 0; pass < 2; ++pass) {
            if (pass == 1 && ty >= 8) break;
            const int r  = ty + pass * 32;
            const int gi = ri0 + r;
            const bool rowok = (unsigned)gi < NXL;
            const float* grow = xc + (rowok ? gi : 0) * NYL;
            char* rb = tbuf + r * ROWB;
#pragma unroll
            for (int m = 0; m < 8; ++m) {
                const int d    = tx + 8 * m;
                const int gcol = A + 2 * d;
                const bool ok  = rowok && ((unsigned)gcol < NYL);
                const int cu   = thcu + 4 * m;
                const int dst  = swz_unit(cu) * 16 + half8;
                __pipeline_memcpy_async(rb + dst,
                                        ok ? grow + gcol : (const float*)xc,
                                        8, ok ? 0 : 8);
            }
            if (tx < 6) {   // tail: dwords 64..69
                const int d    = tx + 64;
                const int gcol = A + 2 * d;
                const bool ok  = rowok && ((unsigned)gcol < NYL);
                const int cu   = thcu + 32;
                const int dst  = swz_unit(cu) * 16 + half8;
                __pipeline_memcpy_async(rb + dst,
                                        ok ? grow + gcol : (const float*)xc,
                                        8, ok ? 0 : 8);
            }
        }
        if (tid < 81) {
            const ull* wsrc = ((const ull*)g_w2)
                            + (size_t)(o * NC_ + c) * 81 + tid;
            __pipeline_memcpy_async(wbuf + wdoff, wsrc, 8);
        }
        __pipeline_commit();
    };

    // per-thread swizzled E unit byte offsets (row-independent)
    int offs[7];
#pragma unroll
    for (int e = 0; e < 7; ++e)
        offs[e] = ty * ROWB + swz_unit(4 * tx + e) * 16;

    ull accA[8], accB[9];
#pragma unroll
    for (int j = 0; j < 8; ++j) accA[j] = 0ull;
#pragma unroll
    for (int i = 0; i < 9; ++i) accB[i] = 0ull;

    stage(0, buf0, wb0);

    for (int c = 0; c < NC_; ++c) {
        __pipeline_wait_prior(0);
        __syncthreads();
        if (c + 1 < NC_)
            stage(c + 1, (c & 1) ? buf0 : buf1, (c & 1) ? wb0 : wb1);

        const char* tb = (c & 1) ? buf1 : buf0;
        const ull*  wv = (const ull*)((c & 1) ? wb1 : wb0);

        if (s_ori[c] & 1) channel_math<1>(tb, wv, offs, accA, accB);
        else              channel_math<0>(tb, wv, offs, accA, accB);

        __syncthreads();   // readers done before next channel overwrites
    }

    // ---- epilogue: merge dual-phase accumulators, write 16 cols ----
    float res[16];
#pragma unroll
    for (int j = 0; j < 8; ++j) {
        float aLo = __uint_as_float((unsigned)(accA[j] & 0xffffffffull));
        float aHi = __uint_as_float((unsigned)(accA[j] >> 32));
        float bHi = __uint_as_float((unsigned)(accB[j] >> 32));
        float bLo = __uint_as_float((unsigned)(accB[j + 1] & 0xffffffffull));
        res[2 * j]     = aLo + bHi;
        res[2 * j + 1] = aHi + bLo;
    }
    float* op = out + ((size_t)(b * NO_ + o) * NXL + (i0 + ty)) * NYL
                    + j0 + tx * 16;
#pragma unroll
    for (int q = 0; q < 4; ++q)
        reinterpret_cast<float4*>(op)[q] =
            make_float4(res[4 * q], res[4 * q + 1],
                        res[4 * q + 2], res[4 * q + 3]);
}

// ---------------------------------------------------------------------------
extern "C" void kernel_launch(void* const* d_in, const int* in_sizes, int n_in,
                              void* d_out, int out_size) {
    const float* x   = (const float*)d_in[0];
    const float* vk  = (const float*)d_in[1];
    const int*   loc = (const int*)d_in[2];
    float* out = (float*)d_out;

    int nloc = in_sizes[2];
    int batch = in_sizes[0] / (NC_ * NXL * NYL);

    cudaFuncSetAttribute(conv_kernel,
                         cudaFuncAttributeMaxDynamicSharedMemorySize,
                         SMEM_BYTES);

    prep_origins<<<(NG_ * 32 + 255) / 256, 256>>>(loc);
    prep_scatter<<<(nloc + 255) / 256, 256>>>(vk, loc, nloc);

    dim3 grid((NXL / TH) * (NYL / TW), NO_, batch);  // (16, 3, 16)
    conv_kernel<<<grid, 256, SMEM_BYTES>>>(x, out);
}

// round 7
// speedup vs baseline: 1.1304x; 1.0265x over previous
#include <cuda_runtime.h>
#include <cuda_pipeline.h>

typedef unsigned long long ull;

// Problem dims
#define NC_  31
#define NXL  256
#define NYL  256
#define NO_  3
#define KXL  17
#define KYL  17
#define NG_  (NO_ * NC_)   // 93
#define WIN_ 9

// Compact weights: per (o,c) group a 9x9 tile of broadcast (v,v) float2 pairs
__device__ float2 g_w2[NG_ * 81];
__device__ int    g_ori[NG_];   // (kx0 << 8) | ky0

// ---------------------------------------------------------------------------
// Fused prep: one warp per group. Phase 1: shfl-min window origin (all lanes
// end with the value). Phase 2: the same warp scatters its 81 relu'd values.
// No cross-warp dependency -> single kernel, no global sync needed.
// ---------------------------------------------------------------------------
__global__ void prep_all(const float* __restrict__ vk,
                         const int* __restrict__ loc) {
    int w    = (blockIdx.x * blockDim.x + threadIdx.x) >> 5;
    int lane = threadIdx.x & 31;
    if (w >= NG_) return;

    int kxm = 1 << 30, kym = 1 << 30;
    int idxs[3]; float vs[3];
#pragma unroll
    for (int s = 0; s < 3; ++s) {
        int t = lane + 32 * s;
        if (t < 81) {
            int idx = loc[w * 81 + t];
            idxs[s] = idx;
            vs[s]   = vk[w * 81 + t];
            int ky = idx % KYL;
            int kx = (idx / KYL) % KXL;
            kxm = min(kxm, kx);
            kym = min(kym, ky);
        }
    }
#pragma unroll
    for (int off = 16; off; off >>= 1) {
        kxm = min(kxm, __shfl_xor_sync(0xffffffffu, kxm, off));
        kym = min(kym, __shfl_xor_sync(0xffffffffu, kym, off));
    }
    if (lane == 0) g_ori[w] = (kxm << 8) | kym;

#pragma unroll
    for (int s = 0; s < 3; ++s) {
        int t = lane + 32 * s;
        if (t < 81) {
            int idx = idxs[s];
            float v = fmaxf(vs[s], 0.0f);
            int ky = idx % KYL;
            int kx = (idx / KYL) % KXL;
            g_w2[w * 81 + (kx - kxm) * WIN_ + (ky - kym)] = make_float2(v, v);
        }
    }
}

// ---------------------------------------------------------------------------
// Main conv. Block = 256 threads, tile 32 rows x 128 cols per (b,o).
// 8B-aligned cp.async staging; residual parity absorbed by dual-phase
// accumulator assignment (two templated channel bodies). Packed fma.rn.f32x2
// math, E operands from XOR-swizzled LDS.128 with next-row software pipeline.
// ONE __syncthreads per channel: stage(c+1) -> compute(c) -> wait -> sync.
// Weights read as LDS.128 pairs (WPAD keeps 16B alignment per tap-row).
// ---------------------------------------------------------------------------
#define TH 32
#define TW 128
#define SRO 40                 // staged rows (TH + 8)
#define SWF 160                // smem row stride in floats
#define ROWB (SWF * 4)         // 640 bytes
#define TILE_B (SRO * ROWB)    // 25600 bytes
#define WPAD 10                // weight row stride in ull
#define WBUF (WIN_ * WPAD)     // 90 ull
#define SMEM_BYTES (2 * TILE_B + 2 * WBUF * 8 + NC_ * 4)  // 52764

#define FMA2(acc, a, b) \
    asm("fma.rn.f32x2 %0, %1, %2, %0;" : "+l"(acc) : "l"(a), "l"(b))

__device__ __forceinline__ int swz_unit(int cu) {
    return cu ^ ((cu >> 3) & 7);
}

// Load one swizzled 16B unit as a pair of ulls.
__device__ __forceinline__ void ldE(const char* p, ull& a, ull& b) {
    longlong2 L = *(const longlong2*)p;
    a = (ull)L.x; b = (ull)L.y;
}

// Channel math, parity variant SV = ky0 & 1.
// P[q] = input float pair (16tx+2q, 16tx+2q+1) of the current tap row.
// accA[j] = (out[2j], out[2j+1]); accB[i] = (out[2i-1], out[2i]).
template<int SV>
__device__ __forceinline__ void channel_math(
        const char* __restrict__ tb, const char* __restrict__ wb,
        const int* offs, ull* accA, ull* accB) {
    ull P[14];
#pragma unroll
    for (int e = 0; e < 5; ++e)
        ldE(tb + offs[e], P[2 * e], P[2 * e + 1]);

#pragma unroll
    for (int u = 0; u < 9; ++u) {
        const int ro = u * ROWB;
        const int rn = ro + ROWB;
        const char* wr = wb + u * (WPAD * 8);
        ull N[10];
        ldE(tb + offs[5] + ro, P[10], P[11]);          // unit 5 JIT
        if (SV == 1)
            ldE(tb + offs[6] + ro, P[12], P[13]);      // unit 6 JIT

        ull w0, w1, w2, w3;
        ldE(wr, w0, w1);                                // taps 0,1
        ldE(wr + 16, w2, w3);                           // taps 2,3

        if (SV == 0) {
#pragma unroll
            for (int j = 0; j < 8; ++j) FMA2(accA[j], P[j], w0);
#pragma unroll
            for (int i = 0; i < 9; ++i) FMA2(accB[i], P[i], w1);
#pragma unroll
            for (int j = 0; j < 8; ++j) FMA2(accA[j], P[1 + j], w2);
#pragma unroll
            for (int i = 0; i < 9; ++i) FMA2(accB[i], P[1 + i], w3);
            if (u < 8) ldE(tb + offs[0] + rn, N[0], N[1]);   // unit0 next
            ldE(wr + 32, w0, w1);                       // taps 4,5
            ldE(wr + 48, w2, w3);                       // taps 6,7
#pragma unroll
            for (int j = 0; j < 8; ++j) FMA2(accA[j], P[2 + j], w0);
#pragma unroll
            for (int i = 0; i < 9; ++i) FMA2(accB[i], P[2 + i], w1);
#pragma unroll
            for (int j = 0; j < 8; ++j) FMA2(accA[j], P[3 + j], w2);
#pragma unroll
            for (int i = 0; i < 9; ++i) FMA2(accB[i], P[3 + i], w3);
            if (u < 8) ldE(tb + offs[1] + rn, N[2], N[3]);   // unit1 next
            const ull w8 = *(const ull*)(wr + 64);      // tap 8
#pragma unroll
            for (int j = 0; j < 8; ++j) FMA2(accA[j], P[4 + j], w8);
        } else {
#pragma unroll
            for (int i = 0; i < 9; ++i) FMA2(accB[i], P[i], w0);
#pragma unroll
            for (int j = 0; j < 8; ++j) FMA2(accA[j], P[1 + j], w1);
#pragma unroll
            for (int i = 0; i < 9; ++i) FMA2(accB[i], P[1 + i], w2);
#pragma unroll
            for (int j = 0; j < 8; ++j) FMA2(accA[j], P[2 + j], w3);
            if (u < 8) ldE(tb + offs[0] + rn, N[0], N[1]);   // unit0 next
            ldE(wr + 32, w0, w1);                       // taps 4,5
            ldE(wr + 48, w2, w3);                       // taps 6,7
#pragma unroll
            for (int i = 0; i < 9; ++i) FMA2(accB[i], P[2 + i], w0);
#pragma unroll
            for (int j = 0; j < 8; ++j) FMA2(accA[j], P[3 + j], w1);
#pragma unroll
            for (int i = 0; i < 9; ++i) FMA2(accB[i], P[3 + i], w2);
#pragma unroll
            for (int j = 0; j < 8; ++j) FMA2(accA[j], P[4 + j], w3);
            if (u < 8) ldE(tb + offs[1] + rn, N[2], N[3]);   // unit1 next
            const ull w8 = *(const ull*)(wr + 64);      // tap 8
#pragma unroll
            for (int i = 0; i < 9; ++i) FMA2(accB[i], P[4 + i], w8);
        }

        if (u < 8) {
            ldE(tb + offs[2] + rn, N[4], N[5]);
            ldE(tb + offs[3] + rn, N[6], N[7]);
            ldE(tb + offs[4] + rn, N[8], N[9]);
#pragma unroll
            for (int k = 0; k < 10; ++k) P[k] = N[k];
        }
    }
}

__global__ void __launch_bounds__(256, 3) conv_kernel(
        const float* __restrict__ x, float* __restrict__ out) {
    extern __shared__ float smem[];
    char* buf0 = (char*)smem;
    char* buf1 = buf0 + TILE_B;
    char* wb0  = buf1 + TILE_B;
    char* wb1  = wb0 + WBUF * 8;
    int*  s_ori = (int*)(wb1 + WBUF * 8);

    const int tid = threadIdx.x;
    const int tx  = tid & 7;          // 16-col group
    const int ty  = tid >> 3;         // output row 0..31

    const int o  = blockIdx.y;
    const int b  = blockIdx.z;
    const int i0 = (blockIdx.x >> 1) * TH;
    const int j0 = (blockIdx.x & 1) * TW;

    if (tid < NC_) s_ori[tid] = g_ori[o * NC_ + tid];
    __syncthreads();

    const float* __restrict__ xb = x + (size_t)b * NC_ * NXL * NYL;
    const int wdoff = ((tid / WIN_) * WPAD + tid % WIN_) * 8;
    const int half8 = (tx & 1) * 8;
    const int thcu  = tx >> 1;

    // ---- async staging of one channel (8B granular, aligned origin) ----
    auto stage = [&](int c, char* tbuf, char* wbuf) {
        const int ori = s_ori[c];
        const int kx0 = ori >> 8, ky0 = ori & 255;
        const int A   = j0 + (ky0 & ~1) - 8;   // even, 8B-aligned gmem origin
        const int ri0 = i0 + kx0 - 8;
        const float* __restrict__ xc = xb + (size_t)c * (NXL * NYL);
#pragma unroll
        for (int pass = 0; pass < 2; ++pass) {
            if (pass == 1 && ty >= 8) break;
            const int r  = ty + pass * 32;
            const int gi = ri0 + r;
            const bool rowok = (unsigned)gi < NXL;
            const float* grow = xc + (rowok ? gi : 0) * NYL;
            char* rb = tbuf + r * ROWB;
#pragma unroll
            for (int m = 0; m < 8; ++m) {
                const int d    = tx + 8 * m;
                const int gcol = A + 2 * d;
                const bool ok  = rowok && ((unsigned)gcol < NYL);
                const int cu   = thcu + 4 * m;
                const int dst  = swz_unit(cu) * 16 + half8;
                __pipeline_memcpy_async(rb + dst,
                                        ok ? grow + gcol : (const float*)xc,
                                        8, ok ? 0 : 8);
            }
            if (tx < 6) {   // tail: dwords 64..69
                const int d    = tx + 64;
                const int gcol = A + 2 * d;
                const bool ok  = rowok && ((unsigned)gcol < NYL);
                const int cu   = thcu + 32;
                const int dst  = swz_unit(cu) * 16 + half8;
                __pipeline_memcpy_async(rb + dst,
                                        ok ? grow + gcol : (const float*)xc,
                                        8, ok ? 0 : 8);
            }
        }
        if (tid < 81) {
            const ull* wsrc = ((const ull*)g_w2)
                            + (size_t)(o * NC_ + c) * 81 + tid;
            __pipeline_memcpy_async(wbuf + wdoff, wsrc, 8);
        }
        __pipeline_commit();
    };

    // per-thread swizzled E unit byte offsets (row-independent)
    int offs[7];
#pragma unroll
    for (int e = 0; e < 7; ++e)
        offs[e] = ty * ROWB + swz_unit(4 * tx + e) * 16;

    ull accA[8], accB[9];
#pragma unroll
    for (int j = 0; j < 8; ++j) accA[j] = 0ull;
#pragma unroll
    for (int i = 0; i < 9; ++i) accB[i] = 0ull;

    stage(0, buf0, wb0);
    __pipeline_wait_prior(0);
    __syncthreads();

    for (int c = 0; c < NC_; ++c) {
        if (c + 1 < NC_)
            stage(c + 1, (c & 1) ? buf0 : buf1, (c & 1) ? wb0 : wb1);

        const char* tb = (c & 1) ? buf1 : buf0;
        const char* wb = (c & 1) ? wb1 : wb0;

        if (s_ori[c] & 1) channel_math<1>(tb, wb, offs, accA, accB);
        else              channel_math<0>(tb, wb, offs, accA, accB);

        // all cp.asyncs for c+1 complete (per thread), then one barrier makes
        // them visible AND retires all readers of buffer c
        __pipeline_wait_prior(0);
        __syncthreads();
    }

    // ---- epilogue: merge dual-phase accumulators, write 16 cols ----
    float res[16];
#pragma unroll
    for (int j = 0; j < 8; ++j) {
        float aLo = __uint_as_float((unsigned)(accA[j] & 0xffffffffull));
        float aHi = __uint_as_float((unsigned)(accA[j] >> 32));
        float bHi = __uint_as_float((unsigned)(accB[j] >> 32));
        float bLo = __uint_as_float((unsigned)(accB[j + 1] & 0xffffffffull));
        res[2 * j]     = aLo + bHi;
        res[2 * j + 1] = aHi + bLo;
    }
    float* op = out + ((size_t)(b * NO_ + o) * NXL + (i0 + ty)) * NYL
                    + j0 + tx * 16;
#pragma unroll
    for (int q = 0; q < 4; ++q)
        reinterpret_cast<float4*>(op)[q] =
            make_float4(res[4 * q], res[4 * q + 1],
                        res[4 * q + 2], res[4 * q + 3]);
}

// ---------------------------------------------------------------------------
extern "C" void kernel_launch(void* const* d_in, const int* in_sizes, int n_in,
                              void* d_out, int out_size) {
    const float* x   = (const float*)d_in[0];
    const float* vk  = (const float*)d_in[1];
    const int*   loc = (const int*)d_in[2];
    float* out = (float*)d_out;

    int batch = in_sizes[0] / (NC_ * NXL * NYL);

    cudaFuncSetAttribute(conv_kernel,
                         cudaFuncAttributeMaxDynamicSharedMemorySize,
                         SMEM_BYTES);

    prep_all<<<(NG_ * 32 + 255) / 256, 256>>>(vk, loc);

    dim3 grid((NXL / TH) * (NYL / TW), NO_, batch);  // (16, 3, 16)
    conv_kernel<<<grid, 256, SMEM_BYTES>>>(x, out);
}